// round 15
// baseline (speedup 1.0000x reference)
#include <cuda_runtime.h>
#include <cuda_fp16.h>
#include <math.h>
#include <stdint.h>

#define C_IN   256
#define C_B    64
#define K_TAP  27
#define N_MAX  200000
#define MAXB   1600
#define BN_EPS 1e-3f

// ---------------- scratch (device globals; no allocation) ----------------
__device__ float  g_h1[(size_t)N_MAX * C_B];    // conv1x1a raw (fp32, for act1 BN)
__device__ __half g_h2h[(size_t)N_MAX * C_B];   // octree conv raw (fp16)
__device__ __half g_h3h[(size_t)N_MAX * C_IN];  // conv1x1b raw (fp16)

__device__ __half g_h1h[(size_t)N_MAX * C_B];   // act1 (fp16 rounded)
__device__ __half g_w3h[K_TAP * C_B * C_B];     // w3 [k][c][d] (fp16 rounded)

__device__ float g_a1[C_B],  g_c1[C_B];
__device__ float g_a2[C_B],  g_c2[C_B];
__device__ float g_a3[C_IN], g_c3[C_IN];

// per-block stats partials (no atomics)
__device__ float g_p1s[MAXB * 64],  g_p1q[MAXB * 64];
__device__ float g_p2s[MAXB * 64],  g_p2q[MAXB * 64];
__device__ float g_p3s[2 * MAXB * 128], g_p3q[2 * MAXB * 128];

__device__ __forceinline__ float gelu_exact(float x) {
    return 0.5f * x * (1.0f + erff(x * 0.70710678118654752440f));
}

// ---------------- mma/ldsm/cp.async helpers ----------------
__device__ __forceinline__ uint32_t smem_u32(const void* p) {
    uint32_t a;
    asm("{ .reg .u64 t; cvta.to.shared.u64 t, %1; cvt.u32.u64 %0, t; }"
        : "=r"(a) : "l"(p));
    return a;
}
__device__ __forceinline__ void ldsm_x4(uint32_t* r, uint32_t addr) {
    asm volatile("ldmatrix.sync.aligned.m8n8.x4.shared.b16 {%0,%1,%2,%3}, [%4];"
                 : "=r"(r[0]), "=r"(r[1]), "=r"(r[2]), "=r"(r[3]) : "r"(addr));
}
__device__ __forceinline__ void ldsm_x4_t(uint32_t* r, uint32_t addr) {
    asm volatile("ldmatrix.sync.aligned.m8n8.x4.trans.shared.b16 {%0,%1,%2,%3}, [%4];"
                 : "=r"(r[0]), "=r"(r[1]), "=r"(r[2]), "=r"(r[3]) : "r"(addr));
}
__device__ __forceinline__ void mma_f16(float* d, const uint32_t* a, const uint32_t* b) {
    asm volatile(
        "mma.sync.aligned.m16n8k16.row.col.f32.f16.f16.f32 "
        "{%0,%1,%2,%3}, {%4,%5,%6,%7}, {%8,%9}, {%0,%1,%2,%3};"
        : "+f"(d[0]), "+f"(d[1]), "+f"(d[2]), "+f"(d[3])
        : "r"(a[0]), "r"(a[1]), "r"(a[2]), "r"(a[3]), "r"(b[0]), "r"(b[1]));
}
__device__ __forceinline__ void cp16(uint32_t dst, const void* src) {
    asm volatile("cp.async.cg.shared.global [%0], [%1], 16;" :: "r"(dst), "l"(src));
}
__device__ __forceinline__ void cp_commit() {
    asm volatile("cp.async.commit_group;" ::: "memory");
}

__device__ __forceinline__ uint32_t hpack(__half a, __half b) {
    unsigned short ua = *(unsigned short*)&a, ub = *(unsigned short*)&b;
    return (uint32_t)ua | ((uint32_t)ub << 16);
}
__device__ __forceinline__ uint2 round4h(float4 v) {
    uint2 r;
    r.x = hpack(__float2half_rn(v.x), __float2half_rn(v.y));
    r.y = hpack(__float2half_rn(v.z), __float2half_rn(v.w));
    return r;
}

// ---------------- epilogue partial-stats (no atomics) ----------------
template<int NT>
__device__ __forceinline__ void epilogue_partials(const float acc[][NT][4],
                                                  int row0_w, int n,
                                                  int lane, int wid, int tid,
                                                  float* __restrict__ gS,
                                                  float* __restrict__ gQ) {
    __shared__ float sS[8][64], sQ[8][64];
    float cs[NT * 2], cq[NT * 2];
    #pragma unroll
    for (int i = 0; i < NT * 2; i++) { cs[i] = 0.f; cq[i] = 0.f; }
    #pragma unroll
    for (int mt = 0; mt < 2; mt++) {
        int r0 = row0_w + mt * 16 + (lane >> 2);
        bool v0 = r0 < n, v1 = (r0 + 8) < n;
        #pragma unroll
        for (int nt = 0; nt < NT; nt++) {
            #pragma unroll
            for (int j = 0; j < 2; j++) {
                float a0 = acc[mt][nt][j], a1 = acc[mt][nt][2 + j];
                if (v0) { cs[nt * 2 + j] += a0; cq[nt * 2 + j] += a0 * a0; }
                if (v1) { cs[nt * 2 + j] += a1; cq[nt * 2 + j] += a1 * a1; }
            }
        }
    }
    #pragma unroll
    for (int m = 4; m <= 16; m <<= 1) {
        #pragma unroll
        for (int i = 0; i < NT * 2; i++) {
            cs[i] += __shfl_xor_sync(0xffffffffu, cs[i], m);
            cq[i] += __shfl_xor_sync(0xffffffffu, cq[i], m);
        }
    }
    __syncthreads();
    if (lane < 4) {
        #pragma unroll
        for (int i = 0; i < NT * 2; i++) {
            int colw = (i >> 1) * 8 + lane * 2 + (i & 1);
            sS[wid][colw] = cs[i];
            sQ[wid][colw] = cq[i];
        }
    }
    __syncthreads();
    if (tid < NT * 16) {
        int grp = tid / (NT * 8);
        int colw = tid % (NT * 8);
        float s = 0.f, q = 0.f;
        #pragma unroll
        for (int w = 0; w < 4; w++) {
            s += sS[grp * 4 + w][colw];
            q += sQ[grp * 4 + w][colw];
        }
        gS[tid] = s;
        gQ[tid] = q;
    }
}

// ---------------- reduce partials + BN finalize ----------------
__global__ void reduce_bnfin64(const float* __restrict__ pS, const float* __restrict__ pQ,
                               int nblk, const float* __restrict__ g,
                               const float* __restrict__ b,
                               float* __restrict__ a, float* __restrict__ c,
                               float inv_n) {
    __shared__ float sm[256], qm[256];
    int col = blockIdx.x, tid = threadIdx.x;
    float s = 0.f, q = 0.f;
    for (int bx = tid; bx < nblk; bx += 256) {
        s += pS[bx * 64 + col];
        q += pQ[bx * 64 + col];
    }
    sm[tid] = s; qm[tid] = q;
    __syncthreads();
    for (int off = 128; off; off >>= 1) {
        if (tid < off) { sm[tid] += sm[tid + off]; qm[tid] += qm[tid + off]; }
        __syncthreads();
    }
    if (tid == 0) {
        float m = sm[0] * inv_n;
        float v = qm[0] * inv_n - m * m;
        if (v < 0.f) v = 0.f;
        float sc = g[col] * rsqrtf(v + BN_EPS);
        a[col] = sc;
        c[col] = b[col] - m * sc;
    }
}
__global__ void reduce_bnfin256(const float* __restrict__ pS, const float* __restrict__ pQ,
                                int nblk, const float* __restrict__ g,
                                const float* __restrict__ b,
                                float* __restrict__ a, float* __restrict__ c,
                                float inv_n) {
    __shared__ float sm[256], qm[256];
    int col = blockIdx.x, tid = threadIdx.x;
    int by = col >> 7, colw = col & 127;
    const float* ps = pS + (size_t)by * MAXB * 128 + colw;
    const float* pq = pQ + (size_t)by * MAXB * 128 + colw;
    float s = 0.f, q = 0.f;
    for (int bx = tid; bx < nblk; bx += 256) {
        s += ps[bx * 128];
        q += pq[bx * 128];
    }
    sm[tid] = s; qm[tid] = q;
    __syncthreads();
    for (int off = 128; off; off >>= 1) {
        if (tid < off) { sm[tid] += sm[tid + off]; qm[tid] += qm[tid + off]; }
        __syncthreads();
    }
    if (tid == 0) {
        float m = sm[0] * inv_n;
        float v = qm[0] * inv_n - m * m;
        if (v < 0.f) v = 0.f;
        float sc = g[col] * rsqrtf(v + BN_EPS);
        a[col] = sc;
        c[col] = b[col] - m * sc;
    }
}

// ---------------- act1: BN+GELU, write fp16 ----------------
__global__ void act1_kernel(long long total) {
    long long i = ((long long)blockIdx.x * blockDim.x + threadIdx.x) * 4;
    if (i >= total) return;
    float4 v = *(const float4*)&g_h1[i];
    int c = (int)(i & (C_B - 1));
    v.x = gelu_exact(fmaf(g_a1[c],     v.x, g_c1[c]));
    v.y = gelu_exact(fmaf(g_a1[c + 1], v.y, g_c1[c + 1]));
    v.z = gelu_exact(fmaf(g_a1[c + 2], v.z, g_c1[c + 2]));
    v.w = gelu_exact(fmaf(g_a1[c + 3], v.w, g_c1[c + 3]));
    *(uint2*)((unsigned short*)g_h1h + i) = round4h(v);
}

// ---------------- w3 round to fp16 (keep [k][c][d] layout) ----------------
__global__ void w3_split_kernel(const float* __restrict__ w3) {
    int i = blockIdx.x * blockDim.x + threadIdx.x;
    if (i >= K_TAP * C_B * C_B) return;
    g_w3h[i] = __float2half_rn(w3[i]);
}

// ============== GEMM1 via mma.sync fp16 (1-term): h1 = data[N,256] @ w1[256,64] ==============
#define G1_A  0
#define G1_B  18432
#define G1_SMEM 27648

__global__ void __launch_bounds__(256) gemm1_mma_kernel(const float* __restrict__ data,
                                                        const float* __restrict__ w1, int n) {
    extern __shared__ char smem[];
    const uint32_t sb = smem_u32(smem);
    const int tid = threadIdx.x;
    const int wid = tid >> 5, lane = tid & 31;
    const int wr = wid & 3, wc = wid >> 2;
    const int row0 = blockIdx.x * 128;

    float acc[2][4][4] = {};
    const uint32_t aOff = (uint32_t)((wr * 32 + (lane & 15)) * 144 + (lane >> 4) * 16);
    const uint32_t bOff = (uint32_t)((lane & 15) * 144 + (wc * 32 + (lane >> 4) * 8) * 2);

    for (int kb = 0; kb < C_IN; kb += 64) {
        #pragma unroll
        for (int j = 0; j < 8; j++) {
            int s = tid + 256 * j;
            int r = s >> 4, f4 = s & 15;
            int rr = row0 + r; if (rr >= n) rr = n - 1;
            float4 v = *(const float4*)(data + (size_t)rr * C_IN + kb + f4 * 4);
            *(uint2*)(smem + G1_A + r * 144 + f4 * 8) = round4h(v);
        }
        #pragma unroll
        for (int j = 0; j < 4; j++) {
            int s = tid + 256 * j;
            int r = s >> 4, f4 = s & 15;
            float4 v = *(const float4*)(w1 + (size_t)(kb + r) * C_B + f4 * 4);
            *(uint2*)(smem + G1_B + r * 144 + f4 * 8) = round4h(v);
        }
        __syncthreads();

        #pragma unroll
        for (int ks = 0; ks < 4; ks++) {
            uint32_t ah[2][4], bh[2][4];
            #pragma unroll
            for (int mt = 0; mt < 2; mt++)
                ldsm_x4(ah[mt], sb + G1_A + aOff + (uint32_t)(mt * 16 * 144 + ks * 32));
            #pragma unroll
            for (int nt2 = 0; nt2 < 2; nt2++)
                ldsm_x4_t(bh[nt2], sb + G1_B + bOff + (uint32_t)(ks * 16 * 144 + nt2 * 32));
            #pragma unroll
            for (int mt = 0; mt < 2; mt++) {
                #pragma unroll
                for (int nt = 0; nt < 4; nt++) {
                    const uint32_t* ph = &bh[nt >> 1][(nt & 1) * 2];
                    mma_f16(acc[mt][nt], ah[mt], ph);
                }
            }
        }
        __syncthreads();
    }

    #pragma unroll
    for (int mt = 0; mt < 2; mt++) {
        int r0 = row0 + wr * 32 + mt * 16 + (lane >> 2);
        #pragma unroll
        for (int nt = 0; nt < 4; nt++) {
            int col = wc * 32 + nt * 8 + (lane & 3) * 2;
            if (r0 < n)
                *(float2*)&g_h1[(size_t)r0 * C_B + col] =
                    make_float2(acc[mt][nt][0], acc[mt][nt][1]);
            if (r0 + 8 < n)
                *(float2*)&g_h1[(size_t)(r0 + 8) * C_B + col] =
                    make_float2(acc[mt][nt][2], acc[mt][nt][3]);
        }
    }
    epilogue_partials<4>(acc, row0 + wr * 32, n, lane, wid, tid,
                         g_p1s + (size_t)blockIdx.x * 64,
                         g_p1q + (size_t)blockIdx.x * 64);
}

// ============== octree conv via mma.sync fp16 (1-term) + cp.async double buffering ==============
#define OB_A  0
#define OB_WH 18432
#define OB_SZ 27648
#define OFF_IDX 0
#define OFF_BUF 13824
#define OCT_SMEM (OFF_BUF + 2 * OB_SZ)   // 69120

__device__ __forceinline__ void issue_tap(uint32_t sb, int buf, int k,
                                          const int* sIdx, int tid) {
    const uint32_t base = sb + OFF_BUF + buf * OB_SZ;
    const int* idx = sIdx + (k << 7);
    #pragma unroll
    for (int j = 0; j < 4; j++) {
        int cid = tid + 256 * j;              // 0..1023
        int r = cid >> 3, q = cid & 7;
        int gr = idx[r];
        cp16(base + OB_A + (uint32_t)(r * 144 + q * 16),
             g_h1h + (size_t)gr * C_B + q * 8);
    }
    #pragma unroll
    for (int j = 0; j < 2; j++) {
        int cid = tid + 256 * j;              // 0..511
        int r = cid >> 3, q = cid & 7;
        cp16(base + OB_WH + (uint32_t)(r * 144 + q * 16),
             g_w3h + (size_t)k * 4096 + cid * 8);
    }
}

__global__ void __launch_bounds__(256) octconv_mma_kernel(const int* __restrict__ neigh,
                                                          int n) {
    extern __shared__ char smem[];
    const uint32_t sb = smem_u32(smem);
    const int tid = threadIdx.x;
    const int wid = tid >> 5, lane = tid & 31;
    const int wr = wid & 3, wc = wid >> 2;
    const int row0 = blockIdx.x * 128;

    int* sIdx = (int*)(smem + OFF_IDX);
    for (int i = tid; i < K_TAP * 128; i += 256) {
        int r = i / K_TAP, k = i - r * K_TAP;
        int nr = row0 + r;
        sIdx[k * 128 + r] = (nr < n) ? neigh[(size_t)nr * K_TAP + k] : 0;
    }
    __syncthreads();

    issue_tap(sb, 0, 0, sIdx, tid);
    cp_commit();

    float acc[2][4][4] = {};
    const uint32_t aOff = (uint32_t)((wr * 32 + (lane & 15)) * 144 + (lane >> 4) * 16);
    const uint32_t bOff = (uint32_t)((lane & 15) * 144 + (wc * 32 + (lane >> 4) * 8) * 2);

    for (int k = 0; k < K_TAP; k++) {
        const int b = k & 1;
        if (k + 1 < K_TAP) {
            issue_tap(sb, b ^ 1, k + 1, sIdx, tid);
            cp_commit();
            asm volatile("cp.async.wait_group 1;" ::: "memory");
        } else {
            asm volatile("cp.async.wait_group 0;" ::: "memory");
        }
        __syncthreads();

        const uint32_t base = sb + OFF_BUF + b * OB_SZ;
        #pragma unroll
        for (int ks = 0; ks < 4; ks++) {
            uint32_t ah[2][4], bh[2][4];
            #pragma unroll
            for (int mt = 0; mt < 2; mt++)
                ldsm_x4(ah[mt], base + OB_A + aOff + (uint32_t)(mt * 16 * 144 + ks * 32));
            #pragma unroll
            for (int nt2 = 0; nt2 < 2; nt2++)
                ldsm_x4_t(bh[nt2], base + OB_WH + bOff + (uint32_t)(ks * 16 * 144 + nt2 * 32));
            #pragma unroll
            for (int mt = 0; mt < 2; mt++) {
                #pragma unroll
                for (int nt = 0; nt < 4; nt++) {
                    const uint32_t* ph = &bh[nt >> 1][(nt & 1) * 2];
                    mma_f16(acc[mt][nt], ah[mt], ph);
                }
            }
        }
        __syncthreads();
    }

    #pragma unroll
    for (int mt = 0; mt < 2; mt++) {
        int r0 = row0 + wr * 32 + mt * 16 + (lane >> 2);
        #pragma unroll
        for (int nt = 0; nt < 4; nt++) {
            int col = wc * 32 + nt * 8 + (lane & 3) * 2;
            if (r0 < n)
                *(__half2*)&g_h2h[(size_t)r0 * C_B + col] =
                    __floats2half2_rn(acc[mt][nt][0], acc[mt][nt][1]);
            if (r0 + 8 < n)
                *(__half2*)&g_h2h[(size_t)(r0 + 8) * C_B + col] =
                    __floats2half2_rn(acc[mt][nt][2], acc[mt][nt][3]);
        }
    }
    epilogue_partials<4>(acc, row0 + wr * 32, n, lane, wid, tid,
                         g_p2s + (size_t)blockIdx.x * 64,
                         g_p2q + (size_t)blockIdx.x * 64);
}

// ============== GEMM2 via mma.sync fp16 (1-term): h3 = act2(h2)[N,64] @ w2[64,256] ==============
#define G2_A  0
#define G2_B  18432
#define G2_SMEM (18432 + 17408)   // 35840

__global__ void __launch_bounds__(256) gemm2_mma_kernel(const float* __restrict__ w2, int n) {
    extern __shared__ char smem[];
    const uint32_t sb = smem_u32(smem);
    const int tid = threadIdx.x;
    const int wid = tid >> 5, lane = tid & 31;
    const int wr = wid & 3, wc = wid >> 2;
    const int row0 = blockIdx.x * 128;
    const int col0 = blockIdx.y * 128;

    // stage A with BN2+GELU, rounded to fp16 (source is fp16 h2)
    #pragma unroll
    for (int j = 0; j < 8; j++) {
        int s = tid + 256 * j;
        int r = s >> 4, f4 = s & 15;
        int rr = row0 + r; if (rr >= n) rr = n - 1;
        const __half2* hp = (const __half2*)(g_h2h + (size_t)rr * C_B + f4 * 4);
        float2 u0 = __half22float2(hp[0]);
        float2 u1 = __half22float2(hp[1]);
        int c = f4 * 4;
        float4 v;
        v.x = gelu_exact(fmaf(g_a2[c],     u0.x, g_c2[c]));
        v.y = gelu_exact(fmaf(g_a2[c + 1], u0.y, g_c2[c + 1]));
        v.z = gelu_exact(fmaf(g_a2[c + 2], u1.x, g_c2[c + 2]));
        v.w = gelu_exact(fmaf(g_a2[c + 3], u1.y, g_c2[c + 3]));
        *(uint2*)(smem + G2_A + r * 144 + f4 * 8) = round4h(v);
    }
    // stage B: w2[0..63][col0..col0+127] (fp16, row stride 272 B)
    #pragma unroll
    for (int j = 0; j < 8; j++) {
        int s = tid + 256 * j;                // 0..2047
        int r = s >> 5, f4 = s & 31;
        float4 v = *(const float4*)(w2 + (size_t)r * C_IN + col0 + f4 * 4);
        *(uint2*)(smem + G2_B + r * 272 + f4 * 8) = round4h(v);
    }
    __syncthreads();

    float acc[2][8][4] = {};
    const uint32_t aOff = (uint32_t)((wr * 32 + (lane & 15)) * 144 + (lane >> 4) * 16);
    const uint32_t bOff = (uint32_t)((lane & 15) * 272 + (wc * 64 + (lane >> 4) * 8) * 2);

    #pragma unroll
    for (int ks = 0; ks < 4; ks++) {
        uint32_t ah[2][4], bh[4][4];
        #pragma unroll
        for (int mt = 0; mt < 2; mt++)
            ldsm_x4(ah[mt], sb + G2_A + aOff + (uint32_t)(mt * 16 * 144 + ks * 32));
        #pragma unroll
        for (int nt2 = 0; nt2 < 4; nt2++)
            ldsm_x4_t(bh[nt2], sb + G2_B + bOff + (uint32_t)(ks * 16 * 272 + nt2 * 32));
        #pragma unroll
        for (int mt = 0; mt < 2; mt++) {
            #pragma unroll
            for (int nt = 0; nt < 8; nt++) {
                const uint32_t* ph = &bh[nt >> 1][(nt & 1) * 2];
                mma_f16(acc[mt][nt], ah[mt], ph);
            }
        }
    }

    #pragma unroll
    for (int mt = 0; mt < 2; mt++) {
        int r0 = row0 + wr * 32 + mt * 16 + (lane >> 2);
        #pragma unroll
        for (int nt = 0; nt < 8; nt++) {
            int col = col0 + wc * 64 + nt * 8 + (lane & 3) * 2;
            if (r0 < n)
                *(__half2*)&g_h3h[(size_t)r0 * C_IN + col] =
                    __floats2half2_rn(acc[mt][nt][0], acc[mt][nt][1]);
            if (r0 + 8 < n)
                *(__half2*)&g_h3h[(size_t)(r0 + 8) * C_IN + col] =
                    __floats2half2_rn(acc[mt][nt][2], acc[mt][nt][3]);
        }
    }
    epilogue_partials<8>(acc, row0 + wr * 32, n, lane, wid, tid,
                         g_p3s + ((size_t)blockIdx.y * MAXB + blockIdx.x) * 128,
                         g_p3q + ((size_t)blockIdx.y * MAXB + blockIdx.x) * 128);
}

// ---------------- epilogue: out = elu(bn3(h3_fp16) + data), 8 elems/thread ----------------
__global__ void final_kernel(const float* __restrict__ data,
                             float* __restrict__ out, long long total) {
    long long i = ((long long)blockIdx.x * blockDim.x + threadIdx.x) * 8;
    if (i >= total) return;
    uint4 hp = *(const uint4*)((const unsigned short*)g_h3h + i);
    float4 d0 = *(const float4*)&data[i];
    float4 d1 = *(const float4*)&data[i + 4];
    int c = (int)(i & (C_IN - 1));
    float2 f0 = __half22float2(*(__half2*)&hp.x);
    float2 f1 = __half22float2(*(__half2*)&hp.y);
    float2 f2 = __half22float2(*(__half2*)&hp.z);
    float2 f3 = __half22float2(*(__half2*)&hp.w);
    float4 h0, h1;
    float x;
    x = fmaf(g_a3[c],     f0.x, g_c3[c])     + d0.x; h0.x = x > 0.f ? x : expm1f(x);
    x = fmaf(g_a3[c + 1], f0.y, g_c3[c + 1]) + d0.y; h0.y = x > 0.f ? x : expm1f(x);
    x = fmaf(g_a3[c + 2], f1.x, g_c3[c + 2]) + d0.z; h0.z = x > 0.f ? x : expm1f(x);
    x = fmaf(g_a3[c + 3], f1.y, g_c3[c + 3]) + d0.w; h0.w = x > 0.f ? x : expm1f(x);
    x = fmaf(g_a3[c + 4], f2.x, g_c3[c + 4]) + d1.x; h1.x = x > 0.f ? x : expm1f(x);
    x = fmaf(g_a3[c + 5], f2.y, g_c3[c + 5]) + d1.y; h1.y = x > 0.f ? x : expm1f(x);
    x = fmaf(g_a3[c + 6], f3.x, g_c3[c + 6]) + d1.z; h1.z = x > 0.f ? x : expm1f(x);
    x = fmaf(g_a3[c + 7], f3.y, g_c3[c + 7]) + d1.w; h1.w = x > 0.f ? x : expm1f(x);
    *(float4*)&out[i]     = h0;
    *(float4*)&out[i + 4] = h1;
}

// ---------------- launch ----------------
extern "C" void kernel_launch(void* const* d_in, const int* in_sizes, int n_in,
                              void* d_out, int out_size) {
    const float* data  = (const float*)d_in[0];
    const int*   neigh = (const int*)d_in[1];
    const float* w1 = (const float*)d_in[2];
    const float* g1 = (const float*)d_in[3];
    const float* b1 = (const float*)d_in[4];
    const float* w3 = (const float*)d_in[5];
    const float* g3 = (const float*)d_in[6];
    const float* b3 = (const float*)d_in[7];
    const float* w2 = (const float*)d_in[8];
    const float* g2 = (const float*)d_in[9];
    const float* b2 = (const float*)d_in[10];
    float* out = (float*)d_out;

    const int n = in_sizes[0] / C_IN;
    const float inv_n = 1.0f / (float)n;
    const int nblk128 = (n + 127) / 128;
    const long long tot_b = (long long)n * C_B;
    const long long tot_c = (long long)n * C_IN;

    float *a1p, *c1p, *a2p, *c2p, *a3p, *c3p;
    cudaGetSymbolAddress((void**)&a1p, g_a1); cudaGetSymbolAddress((void**)&c1p, g_c1);
    cudaGetSymbolAddress((void**)&a2p, g_a2); cudaGetSymbolAddress((void**)&c2p, g_c2);
    cudaGetSymbolAddress((void**)&a3p, g_a3); cudaGetSymbolAddress((void**)&c3p, g_c3);
    float *p1s, *p1q, *p2s, *p2q, *p3s, *p3q;
    cudaGetSymbolAddress((void**)&p1s, g_p1s); cudaGetSymbolAddress((void**)&p1q, g_p1q);
    cudaGetSymbolAddress((void**)&p2s, g_p2s); cudaGetSymbolAddress((void**)&p2q, g_p2q);
    cudaGetSymbolAddress((void**)&p3s, g_p3s); cudaGetSymbolAddress((void**)&p3q, g_p3q);

    cudaFuncSetAttribute(gemm1_mma_kernel,
                         cudaFuncAttributeMaxDynamicSharedMemorySize, G1_SMEM);
    cudaFuncSetAttribute(octconv_mma_kernel,
                         cudaFuncAttributeMaxDynamicSharedMemorySize, OCT_SMEM);
    cudaFuncSetAttribute(gemm2_mma_kernel,
                         cudaFuncAttributeMaxDynamicSharedMemorySize, G2_SMEM);

    w3_split_kernel<<<(K_TAP * C_B * C_B + 255) / 256, 256>>>(w3);

    gemm1_mma_kernel<<<nblk128, 256, G1_SMEM>>>(data, w1, n);
    reduce_bnfin64<<<64, 256>>>(p1s, p1q, nblk128, g1, b1, a1p, c1p, inv_n);
    act1_kernel<<<(int)((tot_b / 4 + 255) / 256), 256>>>(tot_b);

    octconv_mma_kernel<<<nblk128, 256, OCT_SMEM>>>(neigh, n);
    reduce_bnfin64<<<64, 256>>>(p2s, p2q, nblk128, g3, b3, a2p, c2p, inv_n);

    gemm2_mma_kernel<<<dim3(nblk128, 2), 256, G2_SMEM>>>(w2, n);
    reduce_bnfin256<<<256, 256>>>(p3s, p3q, nblk128, g2, b2, a3p, c3p, inv_n);

    final_kernel<<<(int)((tot_c / 8 + 255) / 256), 256>>>(data, out, tot_c);
}

// round 16
// speedup vs baseline: 1.0468x; 1.0468x over previous
#include <cuda_runtime.h>
#include <cuda_fp16.h>
#include <math.h>
#include <stdint.h>

#define C_IN   256
#define C_B    64
#define K_TAP  27
#define N_MAX  200000
#define MAXB   1600
#define BN_EPS 1e-3f

// ---------------- scratch (device globals; no allocation) ----------------
__device__ __half g_h1r[(size_t)N_MAX * C_B];   // conv1x1a raw (fp16, pre-BN)
__device__ float  g_h2[(size_t)N_MAX * C_B];    // octree conv raw (fp32)
__device__ __half g_h3h[(size_t)N_MAX * C_IN];  // conv1x1b raw (fp16)

__device__ __half g_h1h[(size_t)N_MAX * C_B];   // act1 (fp16 rounded)
__device__ __half g_w3h[K_TAP * C_B * C_B];     // w3 [k][c][d] (fp16 rounded)

__device__ float g_a1[C_B],  g_c1[C_B];
__device__ float g_a2[C_B],  g_c2[C_B];
__device__ float g_a3[C_IN], g_c3[C_IN];

// per-block stats partials (no atomics)
__device__ float g_p1s[MAXB * 64],  g_p1q[MAXB * 64];
__device__ float g_p2s[MAXB * 64],  g_p2q[MAXB * 64];
__device__ float g_p3s[2 * MAXB * 128], g_p3q[2 * MAXB * 128];

__device__ __forceinline__ float gelu_exact(float x) {
    return 0.5f * x * (1.0f + erff(x * 0.70710678118654752440f));
}

// ---------------- mma/ldsm/cp.async helpers ----------------
__device__ __forceinline__ uint32_t smem_u32(const void* p) {
    uint32_t a;
    asm("{ .reg .u64 t; cvta.to.shared.u64 t, %1; cvt.u32.u64 %0, t; }"
        : "=r"(a) : "l"(p));
    return a;
}
__device__ __forceinline__ void ldsm_x4(uint32_t* r, uint32_t addr) {
    asm volatile("ldmatrix.sync.aligned.m8n8.x4.shared.b16 {%0,%1,%2,%3}, [%4];"
                 : "=r"(r[0]), "=r"(r[1]), "=r"(r[2]), "=r"(r[3]) : "r"(addr));
}
__device__ __forceinline__ void ldsm_x4_t(uint32_t* r, uint32_t addr) {
    asm volatile("ldmatrix.sync.aligned.m8n8.x4.trans.shared.b16 {%0,%1,%2,%3}, [%4];"
                 : "=r"(r[0]), "=r"(r[1]), "=r"(r[2]), "=r"(r[3]) : "r"(addr));
}
__device__ __forceinline__ void mma_f16(float* d, const uint32_t* a, const uint32_t* b) {
    asm volatile(
        "mma.sync.aligned.m16n8k16.row.col.f32.f16.f16.f32 "
        "{%0,%1,%2,%3}, {%4,%5,%6,%7}, {%8,%9}, {%0,%1,%2,%3};"
        : "+f"(d[0]), "+f"(d[1]), "+f"(d[2]), "+f"(d[3])
        : "r"(a[0]), "r"(a[1]), "r"(a[2]), "r"(a[3]), "r"(b[0]), "r"(b[1]));
}
__device__ __forceinline__ void cp16(uint32_t dst, const void* src) {
    asm volatile("cp.async.cg.shared.global [%0], [%1], 16;" :: "r"(dst), "l"(src));
}
__device__ __forceinline__ void cp_commit() {
    asm volatile("cp.async.commit_group;" ::: "memory");
}

__device__ __forceinline__ uint32_t hpack(__half a, __half b) {
    unsigned short ua = *(unsigned short*)&a, ub = *(unsigned short*)&b;
    return (uint32_t)ua | ((uint32_t)ub << 16);
}
__device__ __forceinline__ uint2 round4h(float4 v) {
    uint2 r;
    r.x = hpack(__float2half_rn(v.x), __float2half_rn(v.y));
    r.y = hpack(__float2half_rn(v.z), __float2half_rn(v.w));
    return r;
}
__device__ __forceinline__ void split4h(float4 v, uint2* hi, uint2* lo) {
    __half h0 = __float2half_rn(v.x), h1 = __float2half_rn(v.y);
    __half h2 = __float2half_rn(v.z), h3 = __float2half_rn(v.w);
    __half l0 = __float2half_rn(v.x - __half2float(h0));
    __half l1 = __float2half_rn(v.y - __half2float(h1));
    __half l2 = __float2half_rn(v.z - __half2float(h2));
    __half l3 = __float2half_rn(v.w - __half2float(h3));
    hi->x = hpack(h0, h1); hi->y = hpack(h2, h3);
    lo->x = hpack(l0, l1); lo->y = hpack(l2, l3);
}

// ---------------- epilogue partial-stats (no atomics) ----------------
template<int NT>
__device__ __forceinline__ void epilogue_partials(const float acc[][NT][4],
                                                  int row0_w, int n,
                                                  int lane, int wid, int tid,
                                                  float* __restrict__ gS,
                                                  float* __restrict__ gQ) {
    __shared__ float sS[8][64], sQ[8][64];
    float cs[NT * 2], cq[NT * 2];
    #pragma unroll
    for (int i = 0; i < NT * 2; i++) { cs[i] = 0.f; cq[i] = 0.f; }
    #pragma unroll
    for (int mt = 0; mt < 2; mt++) {
        int r0 = row0_w + mt * 16 + (lane >> 2);
        bool v0 = r0 < n, v1 = (r0 + 8) < n;
        #pragma unroll
        for (int nt = 0; nt < NT; nt++) {
            #pragma unroll
            for (int j = 0; j < 2; j++) {
                float a0 = acc[mt][nt][j], a1 = acc[mt][nt][2 + j];
                if (v0) { cs[nt * 2 + j] += a0; cq[nt * 2 + j] += a0 * a0; }
                if (v1) { cs[nt * 2 + j] += a1; cq[nt * 2 + j] += a1 * a1; }
            }
        }
    }
    #pragma unroll
    for (int m = 4; m <= 16; m <<= 1) {
        #pragma unroll
        for (int i = 0; i < NT * 2; i++) {
            cs[i] += __shfl_xor_sync(0xffffffffu, cs[i], m);
            cq[i] += __shfl_xor_sync(0xffffffffu, cq[i], m);
        }
    }
    __syncthreads();
    if (lane < 4) {
        #pragma unroll
        for (int i = 0; i < NT * 2; i++) {
            int colw = (i >> 1) * 8 + lane * 2 + (i & 1);
            sS[wid][colw] = cs[i];
            sQ[wid][colw] = cq[i];
        }
    }
    __syncthreads();
    if (tid < NT * 16) {
        int grp = tid / (NT * 8);
        int colw = tid % (NT * 8);
        float s = 0.f, q = 0.f;
        #pragma unroll
        for (int w = 0; w < 4; w++) {
            s += sS[grp * 4 + w][colw];
            q += sQ[grp * 4 + w][colw];
        }
        gS[tid] = s;
        gQ[tid] = q;
    }
}

// ---------------- reduce partials + BN finalize ----------------
__global__ void reduce_bnfin64(const float* __restrict__ pS, const float* __restrict__ pQ,
                               int nblk, const float* __restrict__ g,
                               const float* __restrict__ b,
                               float* __restrict__ a, float* __restrict__ c,
                               float inv_n) {
    __shared__ float sm[256], qm[256];
    int col = blockIdx.x, tid = threadIdx.x;
    float s = 0.f, q = 0.f;
    for (int bx = tid; bx < nblk; bx += 256) {
        s += pS[bx * 64 + col];
        q += pQ[bx * 64 + col];
    }
    sm[tid] = s; qm[tid] = q;
    __syncthreads();
    for (int off = 128; off; off >>= 1) {
        if (tid < off) { sm[tid] += sm[tid + off]; qm[tid] += qm[tid + off]; }
        __syncthreads();
    }
    if (tid == 0) {
        float m = sm[0] * inv_n;
        float v = qm[0] * inv_n - m * m;
        if (v < 0.f) v = 0.f;
        float sc = g[col] * rsqrtf(v + BN_EPS);
        a[col] = sc;
        c[col] = b[col] - m * sc;
    }
}
__global__ void reduce_bnfin256(const float* __restrict__ pS, const float* __restrict__ pQ,
                                int nblk, const float* __restrict__ g,
                                const float* __restrict__ b,
                                float* __restrict__ a, float* __restrict__ c,
                                float inv_n) {
    __shared__ float sm[256], qm[256];
    int col = blockIdx.x, tid = threadIdx.x;
    int by = col >> 7, colw = col & 127;
    const float* ps = pS + (size_t)by * MAXB * 128 + colw;
    const float* pq = pQ + (size_t)by * MAXB * 128 + colw;
    float s = 0.f, q = 0.f;
    for (int bx = tid; bx < nblk; bx += 256) {
        s += ps[bx * 128];
        q += pq[bx * 128];
    }
    sm[tid] = s; qm[tid] = q;
    __syncthreads();
    for (int off = 128; off; off >>= 1) {
        if (tid < off) { sm[tid] += sm[tid + off]; qm[tid] += qm[tid + off]; }
        __syncthreads();
    }
    if (tid == 0) {
        float m = sm[0] * inv_n;
        float v = qm[0] * inv_n - m * m;
        if (v < 0.f) v = 0.f;
        float sc = g[col] * rsqrtf(v + BN_EPS);
        a[col] = sc;
        c[col] = b[col] - m * sc;
    }
}

// ---------------- act1: BN+GELU from fp16 raw h1, write fp16 ----------------
__global__ void act1_kernel(long long total) {
    long long i = ((long long)blockIdx.x * blockDim.x + threadIdx.x) * 4;
    if (i >= total) return;
    uint2 hp = *(const uint2*)((const unsigned short*)g_h1r + i);
    float2 u0 = __half22float2(*(__half2*)&hp.x);
    float2 u1 = __half22float2(*(__half2*)&hp.y);
    int c = (int)(i & (C_B - 1));
    float4 v;
    v.x = gelu_exact(fmaf(g_a1[c],     u0.x, g_c1[c]));
    v.y = gelu_exact(fmaf(g_a1[c + 1], u0.y, g_c1[c + 1]));
    v.z = gelu_exact(fmaf(g_a1[c + 2], u1.x, g_c1[c + 2]));
    v.w = gelu_exact(fmaf(g_a1[c + 3], u1.y, g_c1[c + 3]));
    *(uint2*)((unsigned short*)g_h1h + i) = round4h(v);
}

// ---------------- w3 round to fp16 (keep [k][c][d] layout) ----------------
__global__ void w3_split_kernel(const float* __restrict__ w3) {
    int i = blockIdx.x * blockDim.x + threadIdx.x;
    if (i >= K_TAP * C_B * C_B) return;
    g_w3h[i] = __float2half_rn(w3[i]);
}

// ============== GEMM1 via mma.sync fp16 (2-term W): h1 = data[N,256] @ w1[256,64] ==============
#define G1_A  0
#define G1_BH 18432
#define G1_BL 27648
#define G1_SMEM 36864

__global__ void __launch_bounds__(256) gemm1_mma_kernel(const float* __restrict__ data,
                                                        const float* __restrict__ w1, int n) {
    extern __shared__ char smem[];
    const uint32_t sb = smem_u32(smem);
    const int tid = threadIdx.x;
    const int wid = tid >> 5, lane = tid & 31;
    const int wr = wid & 3, wc = wid >> 2;
    const int row0 = blockIdx.x * 128;

    float acc[2][4][4] = {};
    const uint32_t aOff = (uint32_t)((wr * 32 + (lane & 15)) * 144 + (lane >> 4) * 16);
    const uint32_t bOff = (uint32_t)((lane & 15) * 144 + (wc * 32 + (lane >> 4) * 8) * 2);

    for (int kb = 0; kb < C_IN; kb += 64) {
        #pragma unroll
        for (int j = 0; j < 8; j++) {
            int s = tid + 256 * j;
            int r = s >> 4, f4 = s & 15;
            int rr = row0 + r; if (rr >= n) rr = n - 1;
            float4 v = *(const float4*)(data + (size_t)rr * C_IN + kb + f4 * 4);
            *(uint2*)(smem + G1_A + r * 144 + f4 * 8) = round4h(v);
        }
        #pragma unroll
        for (int j = 0; j < 4; j++) {
            int s = tid + 256 * j;
            int r = s >> 4, f4 = s & 15;
            float4 v = *(const float4*)(w1 + (size_t)(kb + r) * C_B + f4 * 4);
            uint2 hi, lo; split4h(v, &hi, &lo);
            *(uint2*)(smem + G1_BH + r * 144 + f4 * 8) = hi;
            *(uint2*)(smem + G1_BL + r * 144 + f4 * 8) = lo;
        }
        __syncthreads();

        #pragma unroll
        for (int ks = 0; ks < 4; ks++) {
            uint32_t ah[2][4], bh[2][4], bl[2][4];
            #pragma unroll
            for (int mt = 0; mt < 2; mt++)
                ldsm_x4(ah[mt], sb + G1_A + aOff + (uint32_t)(mt * 16 * 144 + ks * 32));
            #pragma unroll
            for (int nt2 = 0; nt2 < 2; nt2++) {
                uint32_t bd = sb + G1_BH + bOff + (uint32_t)(ks * 16 * 144 + nt2 * 32);
                ldsm_x4_t(bh[nt2], bd);
                ldsm_x4_t(bl[nt2], bd + (G1_BL - G1_BH));
            }
            #pragma unroll
            for (int mt = 0; mt < 2; mt++) {
                #pragma unroll
                for (int nt = 0; nt < 4; nt++) {
                    const uint32_t* ph = &bh[nt >> 1][(nt & 1) * 2];
                    const uint32_t* pl = &bl[nt >> 1][(nt & 1) * 2];
                    mma_f16(acc[mt][nt], ah[mt], ph);
                    mma_f16(acc[mt][nt], ah[mt], pl);
                }
            }
        }
        __syncthreads();
    }

    #pragma unroll
    for (int mt = 0; mt < 2; mt++) {
        int r0 = row0 + wr * 32 + mt * 16 + (lane >> 2);
        #pragma unroll
        for (int nt = 0; nt < 4; nt++) {
            int col = wc * 32 + nt * 8 + (lane & 3) * 2;
            if (r0 < n)
                *(__half2*)&g_h1r[(size_t)r0 * C_B + col] =
                    __floats2half2_rn(acc[mt][nt][0], acc[mt][nt][1]);
            if (r0 + 8 < n)
                *(__half2*)&g_h1r[(size_t)(r0 + 8) * C_B + col] =
                    __floats2half2_rn(acc[mt][nt][2], acc[mt][nt][3]);
        }
    }
    epilogue_partials<4>(acc, row0 + wr * 32, n, lane, wid, tid,
                         g_p1s + (size_t)blockIdx.x * 64,
                         g_p1q + (size_t)blockIdx.x * 64);
}

// ============== octree conv via mma.sync fp16 (1-term) + cp.async double buffering ==============
#define OB_A  0
#define OB_WH 18432
#define OB_SZ 27648
#define OFF_IDX 0
#define OFF_BUF 13824
#define OCT_SMEM (OFF_BUF + 2 * OB_SZ)   // 69120

__device__ __forceinline__ void issue_tap(uint32_t sb, int buf, int k,
                                          const int* sIdx, int tid) {
    const uint32_t base = sb + OFF_BUF + buf * OB_SZ;
    const int* idx = sIdx + (k << 7);
    #pragma unroll
    for (int j = 0; j < 4; j++) {
        int cid = tid + 256 * j;              // 0..1023
        int r = cid >> 3, q = cid & 7;
        int gr = idx[r];
        cp16(base + OB_A + (uint32_t)(r * 144 + q * 16),
             g_h1h + (size_t)gr * C_B + q * 8);
    }
    #pragma unroll
    for (int j = 0; j < 2; j++) {
        int cid = tid + 256 * j;              // 0..511
        int r = cid >> 3, q = cid & 7;
        cp16(base + OB_WH + (uint32_t)(r * 144 + q * 16),
             g_w3h + (size_t)k * 4096 + cid * 8);
    }
}

__global__ void __launch_bounds__(256) octconv_mma_kernel(const int* __restrict__ neigh,
                                                          int n) {
    extern __shared__ char smem[];
    const uint32_t sb = smem_u32(smem);
    const int tid = threadIdx.x;
    const int wid = tid >> 5, lane = tid & 31;
    const int wr = wid & 3, wc = wid >> 2;
    const int row0 = blockIdx.x * 128;

    int* sIdx = (int*)(smem + OFF_IDX);
    for (int i = tid; i < K_TAP * 128; i += 256) {
        int r = i / K_TAP, k = i - r * K_TAP;
        int nr = row0 + r;
        sIdx[k * 128 + r] = (nr < n) ? neigh[(size_t)nr * K_TAP + k] : 0;
    }
    __syncthreads();

    issue_tap(sb, 0, 0, sIdx, tid);
    cp_commit();

    float acc[2][4][4] = {};
    const uint32_t aOff = (uint32_t)((wr * 32 + (lane & 15)) * 144 + (lane >> 4) * 16);
    const uint32_t bOff = (uint32_t)((lane & 15) * 144 + (wc * 32 + (lane >> 4) * 8) * 2);

    for (int k = 0; k < K_TAP; k++) {
        const int b = k & 1;
        if (k + 1 < K_TAP) {
            issue_tap(sb, b ^ 1, k + 1, sIdx, tid);
            cp_commit();
            asm volatile("cp.async.wait_group 1;" ::: "memory");
        } else {
            asm volatile("cp.async.wait_group 0;" ::: "memory");
        }
        __syncthreads();

        const uint32_t base = sb + OFF_BUF + b * OB_SZ;
        #pragma unroll
        for (int ks = 0; ks < 4; ks++) {
            uint32_t ah[2][4], bh[2][4];
            #pragma unroll
            for (int mt = 0; mt < 2; mt++)
                ldsm_x4(ah[mt], base + OB_A + aOff + (uint32_t)(mt * 16 * 144 + ks * 32));
            #pragma unroll
            for (int nt2 = 0; nt2 < 2; nt2++)
                ldsm_x4_t(bh[nt2], base + OB_WH + bOff + (uint32_t)(ks * 16 * 144 + nt2 * 32));
            #pragma unroll
            for (int mt = 0; mt < 2; mt++) {
                #pragma unroll
                for (int nt = 0; nt < 4; nt++) {
                    const uint32_t* ph = &bh[nt >> 1][(nt & 1) * 2];
                    mma_f16(acc[mt][nt], ah[mt], ph);
                }
            }
        }
        __syncthreads();
    }

    #pragma unroll
    for (int mt = 0; mt < 2; mt++) {
        int r0 = row0 + wr * 32 + mt * 16 + (lane >> 2);
        #pragma unroll
        for (int nt = 0; nt < 4; nt++) {
            int col = wc * 32 + nt * 8 + (lane & 3) * 2;
            if (r0 < n)
                *(float2*)&g_h2[(size_t)r0 * C_B + col] =
                    make_float2(acc[mt][nt][0], acc[mt][nt][1]);
            if (r0 + 8 < n)
                *(float2*)&g_h2[(size_t)(r0 + 8) * C_B + col] =
                    make_float2(acc[mt][nt][2], acc[mt][nt][3]);
        }
    }
    epilogue_partials<4>(acc, row0 + wr * 32, n, lane, wid, tid,
                         g_p2s + (size_t)blockIdx.x * 64,
                         g_p2q + (size_t)blockIdx.x * 64);
}

// ============== GEMM2 via mma.sync fp16 (2-term W): h3 = act2(h2)[N,64] @ w2[64,256] ==============
#define G2_A  0
#define G2_BH 18432
#define G2_BL (18432 + 17408)
#define G2_SMEM (18432 + 2 * 17408)   // 53248

__global__ void __launch_bounds__(256) gemm2_mma_kernel(const float* __restrict__ w2, int n) {
    extern __shared__ char smem[];
    const uint32_t sb = smem_u32(smem);
    const int tid = threadIdx.x;
    const int wid = tid >> 5, lane = tid & 31;
    const int wr = wid & 3, wc = wid >> 2;
    const int row0 = blockIdx.x * 128;
    const int col0 = blockIdx.y * 128;

    #pragma unroll
    for (int j = 0; j < 8; j++) {
        int s = tid + 256 * j;
        int r = s >> 4, f4 = s & 15;
        int rr = row0 + r; if (rr >= n) rr = n - 1;
        float4 v = *(const float4*)(g_h2 + (size_t)rr * C_B + f4 * 4);
        int c = f4 * 4;
        v.x = gelu_exact(fmaf(g_a2[c],     v.x, g_c2[c]));
        v.y = gelu_exact(fmaf(g_a2[c + 1], v.y, g_c2[c + 1]));
        v.z = gelu_exact(fmaf(g_a2[c + 2], v.z, g_c2[c + 2]));
        v.w = gelu_exact(fmaf(g_a2[c + 3], v.w, g_c2[c + 3]));
        *(uint2*)(smem + G2_A + r * 144 + f4 * 8) = round4h(v);
    }
    #pragma unroll
    for (int j = 0; j < 8; j++) {
        int s = tid + 256 * j;                // 0..2047
        int r = s >> 5, f4 = s & 31;
        float4 v = *(const float4*)(w2 + (size_t)r * C_IN + col0 + f4 * 4);
        uint2 hi, lo; split4h(v, &hi, &lo);
        *(uint2*)(smem + G2_BH + r * 272 + f4 * 8) = hi;
        *(uint2*)(smem + G2_BL + r * 272 + f4 * 8) = lo;
    }
    __syncthreads();

    float acc[2][8][4] = {};
    const uint32_t aOff = (uint32_t)((wr * 32 + (lane & 15)) * 144 + (lane >> 4) * 16);
    const uint32_t bOff = (uint32_t)((lane & 15) * 272 + (wc * 64 + (lane >> 4) * 8) * 2);

    #pragma unroll
    for (int ks = 0; ks < 4; ks++) {
        uint32_t ah[2][4], bh[4][4], bl[4][4];
        #pragma unroll
        for (int mt = 0; mt < 2; mt++)
            ldsm_x4(ah[mt], sb + G2_A + aOff + (uint32_t)(mt * 16 * 144 + ks * 32));
        #pragma unroll
        for (int nt2 = 0; nt2 < 4; nt2++) {
            uint32_t bd = sb + G2_BH + bOff + (uint32_t)(ks * 16 * 272 + nt2 * 32);
            ldsm_x4_t(bh[nt2], bd);
            ldsm_x4_t(bl[nt2], bd + (G2_BL - G2_BH));
        }
        #pragma unroll
        for (int mt = 0; mt < 2; mt++) {
            #pragma unroll
            for (int nt = 0; nt < 8; nt++) {
                const uint32_t* ph = &bh[nt >> 1][(nt & 1) * 2];
                const uint32_t* pl = &bl[nt >> 1][(nt & 1) * 2];
                mma_f16(acc[mt][nt], ah[mt], ph);
                mma_f16(acc[mt][nt], ah[mt], pl);
            }
        }
    }

    #pragma unroll
    for (int mt = 0; mt < 2; mt++) {
        int r0 = row0 + wr * 32 + mt * 16 + (lane >> 2);
        #pragma unroll
        for (int nt = 0; nt < 8; nt++) {
            int col = col0 + wc * 64 + nt * 8 + (lane & 3) * 2;
            if (r0 < n)
                *(__half2*)&g_h3h[(size_t)r0 * C_IN + col] =
                    __floats2half2_rn(acc[mt][nt][0], acc[mt][nt][1]);
            if (r0 + 8 < n)
                *(__half2*)&g_h3h[(size_t)(r0 + 8) * C_IN + col] =
                    __floats2half2_rn(acc[mt][nt][2], acc[mt][nt][3]);
        }
    }
    epilogue_partials<8>(acc, row0 + wr * 32, n, lane, wid, tid,
                         g_p3s + ((size_t)blockIdx.y * MAXB + blockIdx.x) * 128,
                         g_p3q + ((size_t)blockIdx.y * MAXB + blockIdx.x) * 128);
}

// ---------------- epilogue: out = elu(bn3(h3_fp16) + data) ----------------
__global__ void final_kernel(const float* __restrict__ data,
                             float* __restrict__ out, long long total) {
    long long i = ((long long)blockIdx.x * blockDim.x + threadIdx.x) * 4;
    if (i >= total) return;
    uint2 hp = *(const uint2*)((const unsigned short*)g_h3h + i);
    float2 f0 = __half22float2(*(__half2*)&hp.x);
    float2 f1 = __half22float2(*(__half2*)&hp.y);
    float4 d = *(const float4*)&data[i];
    int c = (int)(i & (C_IN - 1));
    float4 h;
    float x;
    x = fmaf(g_a3[c],     f0.x, g_c3[c])     + d.x; h.x = x > 0.f ? x : expm1f(x);
    x = fmaf(g_a3[c + 1], f0.y, g_c3[c + 1]) + d.y; h.y = x > 0.f ? x : expm1f(x);
    x = fmaf(g_a3[c + 2], f1.x, g_c3[c + 2]) + d.z; h.z = x > 0.f ? x : expm1f(x);
    x = fmaf(g_a3[c + 3], f1.y, g_c3[c + 3]) + d.w; h.w = x > 0.f ? x : expm1f(x);
    *(float4*)&out[i] = h;
}

// ---------------- launch ----------------
extern "C" void kernel_launch(void* const* d_in, const int* in_sizes, int n_in,
                              void* d_out, int out_size) {
    const float* data  = (const float*)d_in[0];
    const int*   neigh = (const int*)d_in[1];
    const float* w1 = (const float*)d_in[2];
    const float* g1 = (const float*)d_in[3];
    const float* b1 = (const float*)d_in[4];
    const float* w3 = (const float*)d_in[5];
    const float* g3 = (const float*)d_in[6];
    const float* b3 = (const float*)d_in[7];
    const float* w2 = (const float*)d_in[8];
    const float* g2 = (const float*)d_in[9];
    const float* b2 = (const float*)d_in[10];
    float* out = (float*)d_out;

    const int n = in_sizes[0] / C_IN;
    const float inv_n = 1.0f / (float)n;
    const int nblk128 = (n + 127) / 128;
    const long long tot_b = (long long)n * C_B;
    const long long tot_c = (long long)n * C_IN;

    float *a1p, *c1p, *a2p, *c2p, *a3p, *c3p;
    cudaGetSymbolAddress((void**)&a1p, g_a1); cudaGetSymbolAddress((void**)&c1p, g_c1);
    cudaGetSymbolAddress((void**)&a2p, g_a2); cudaGetSymbolAddress((void**)&c2p, g_c2);
    cudaGetSymbolAddress((void**)&a3p, g_a3); cudaGetSymbolAddress((void**)&c3p, g_c3);
    float *p1s, *p1q, *p2s, *p2q, *p3s, *p3q;
    cudaGetSymbolAddress((void**)&p1s, g_p1s); cudaGetSymbolAddress((void**)&p1q, g_p1q);
    cudaGetSymbolAddress((void**)&p2s, g_p2s); cudaGetSymbolAddress((void**)&p2q, g_p2q);
    cudaGetSymbolAddress((void**)&p3s, g_p3s); cudaGetSymbolAddress((void**)&p3q, g_p3q);

    cudaFuncSetAttribute(gemm1_mma_kernel,
                         cudaFuncAttributeMaxDynamicSharedMemorySize, G1_SMEM);
    cudaFuncSetAttribute(octconv_mma_kernel,
                         cudaFuncAttributeMaxDynamicSharedMemorySize, OCT_SMEM);
    cudaFuncSetAttribute(gemm2_mma_kernel,
                         cudaFuncAttributeMaxDynamicSharedMemorySize, G2_SMEM);

    w3_split_kernel<<<(K_TAP * C_B * C_B + 255) / 256, 256>>>(w3);

    gemm1_mma_kernel<<<nblk128, 256, G1_SMEM>>>(data, w1, n);
    reduce_bnfin64<<<64, 256>>>(p1s, p1q, nblk128, g1, b1, a1p, c1p, inv_n);
    act1_kernel<<<(int)((tot_b / 4 + 255) / 256), 256>>>(tot_b);

    octconv_mma_kernel<<<nblk128, 256, OCT_SMEM>>>(neigh, n);
    reduce_bnfin64<<<64, 256>>>(p2s, p2q, nblk128, g3, b3, a2p, c2p, inv_n);

    gemm2_mma_kernel<<<dim3(nblk128, 2), 256, G2_SMEM>>>(w2, n);
    reduce_bnfin256<<<256, 256>>>(p3s, p3q, nblk128, g2, b2, a3p, c3p, inv_n);

    final_kernel<<<(int)((tot_c / 4 + 255) / 256), 256>>>(data, out, tot_c);
}

// round 17
// speedup vs baseline: 1.0594x; 1.0120x over previous
#include <cuda_runtime.h>
#include <cuda_fp16.h>
#include <math.h>
#include <stdint.h>

#define C_IN   256
#define C_B    64
#define K_TAP  27
#define N_MAX  200000
#define MAXB   1600
#define BN_EPS 1e-3f

// ---------------- scratch (device globals; no allocation) ----------------
__device__ __half g_h1r[(size_t)N_MAX * C_B];   // conv1x1a raw (fp16, pre-BN)
__device__ float  g_h2[(size_t)N_MAX * C_B];    // octree conv raw (fp32)
__device__ __half g_h3h[(size_t)N_MAX * C_IN];  // conv1x1b raw (fp16)

__device__ __half g_h1h[(size_t)N_MAX * C_B];   // act1 (fp16 rounded)
__device__ __half g_w3h[K_TAP * C_B * C_B];     // w3 [k][c][d] (fp16 rounded)

__device__ float g_a1[C_B],  g_c1[C_B];
__device__ float g_a2[C_B],  g_c2[C_B];
__device__ float g_a3[C_IN], g_c3[C_IN];

// per-block stats partials (no atomics)
__device__ float g_p1s[MAXB * 64],  g_p1q[MAXB * 64];
__device__ float g_p2s[MAXB * 64],  g_p2q[MAXB * 64];
__device__ float g_p3s[2 * MAXB * 128], g_p3q[2 * MAXB * 128];

__device__ __forceinline__ float gelu_exact(float x) {
    return 0.5f * x * (1.0f + erff(x * 0.70710678118654752440f));
}

// ---------------- mma/ldsm/cp.async helpers ----------------
__device__ __forceinline__ uint32_t smem_u32(const void* p) {
    uint32_t a;
    asm("{ .reg .u64 t; cvta.to.shared.u64 t, %1; cvt.u32.u64 %0, t; }"
        : "=r"(a) : "l"(p));
    return a;
}
__device__ __forceinline__ void ldsm_x4(uint32_t* r, uint32_t addr) {
    asm volatile("ldmatrix.sync.aligned.m8n8.x4.shared.b16 {%0,%1,%2,%3}, [%4];"
                 : "=r"(r[0]), "=r"(r[1]), "=r"(r[2]), "=r"(r[3]) : "r"(addr));
}
__device__ __forceinline__ void ldsm_x4_t(uint32_t* r, uint32_t addr) {
    asm volatile("ldmatrix.sync.aligned.m8n8.x4.trans.shared.b16 {%0,%1,%2,%3}, [%4];"
                 : "=r"(r[0]), "=r"(r[1]), "=r"(r[2]), "=r"(r[3]) : "r"(addr));
}
__device__ __forceinline__ void mma_f16(float* d, const uint32_t* a, const uint32_t* b) {
    asm volatile(
        "mma.sync.aligned.m16n8k16.row.col.f32.f16.f16.f32 "
        "{%0,%1,%2,%3}, {%4,%5,%6,%7}, {%8,%9}, {%0,%1,%2,%3};"
        : "+f"(d[0]), "+f"(d[1]), "+f"(d[2]), "+f"(d[3])
        : "r"(a[0]), "r"(a[1]), "r"(a[2]), "r"(a[3]), "r"(b[0]), "r"(b[1]));
}
__device__ __forceinline__ void cp16(uint32_t dst, const void* src) {
    asm volatile("cp.async.cg.shared.global [%0], [%1], 16;" :: "r"(dst), "l"(src));
}
__device__ __forceinline__ void cp_commit() {
    asm volatile("cp.async.commit_group;" ::: "memory");
}

__device__ __forceinline__ uint32_t hpack(__half a, __half b) {
    unsigned short ua = *(unsigned short*)&a, ub = *(unsigned short*)&b;
    return (uint32_t)ua | ((uint32_t)ub << 16);
}
__device__ __forceinline__ uint2 round4h(float4 v) {
    uint2 r;
    r.x = hpack(__float2half_rn(v.x), __float2half_rn(v.y));
    r.y = hpack(__float2half_rn(v.z), __float2half_rn(v.w));
    return r;
}
__device__ __forceinline__ void split4h(float4 v, uint2* hi, uint2* lo) {
    __half h0 = __float2half_rn(v.x), h1 = __float2half_rn(v.y);
    __half h2 = __float2half_rn(v.z), h3 = __float2half_rn(v.w);
    __half l0 = __float2half_rn(v.x - __half2float(h0));
    __half l1 = __float2half_rn(v.y - __half2float(h1));
    __half l2 = __float2half_rn(v.z - __half2float(h2));
    __half l3 = __float2half_rn(v.w - __half2float(h3));
    hi->x = hpack(h0, h1); hi->y = hpack(h2, h3);
    lo->x = hpack(l0, l1); lo->y = hpack(l2, l3);
}

// ---------------- epilogue partial-stats (no atomics) ----------------
template<int NT>
__device__ __forceinline__ void epilogue_partials(const float acc[][NT][4],
                                                  int row0_w, int n,
                                                  int lane, int wid, int tid,
                                                  float* __restrict__ gS,
                                                  float* __restrict__ gQ) {
    __shared__ float sS[8][64], sQ[8][64];
    float cs[NT * 2], cq[NT * 2];
    #pragma unroll
    for (int i = 0; i < NT * 2; i++) { cs[i] = 0.f; cq[i] = 0.f; }
    #pragma unroll
    for (int mt = 0; mt < 2; mt++) {
        int r0 = row0_w + mt * 16 + (lane >> 2);
        bool v0 = r0 < n, v1 = (r0 + 8) < n;
        #pragma unroll
        for (int nt = 0; nt < NT; nt++) {
            #pragma unroll
            for (int j = 0; j < 2; j++) {
                float a0 = acc[mt][nt][j], a1 = acc[mt][nt][2 + j];
                if (v0) { cs[nt * 2 + j] += a0; cq[nt * 2 + j] += a0 * a0; }
                if (v1) { cs[nt * 2 + j] += a1; cq[nt * 2 + j] += a1 * a1; }
            }
        }
    }
    #pragma unroll
    for (int m = 4; m <= 16; m <<= 1) {
        #pragma unroll
        for (int i = 0; i < NT * 2; i++) {
            cs[i] += __shfl_xor_sync(0xffffffffu, cs[i], m);
            cq[i] += __shfl_xor_sync(0xffffffffu, cq[i], m);
        }
    }
    __syncthreads();
    if (lane < 4) {
        #pragma unroll
        for (int i = 0; i < NT * 2; i++) {
            int colw = (i >> 1) * 8 + lane * 2 + (i & 1);
            sS[wid][colw] = cs[i];
            sQ[wid][colw] = cq[i];
        }
    }
    __syncthreads();
    if (tid < NT * 16) {
        int grp = tid / (NT * 8);
        int colw = tid % (NT * 8);
        float s = 0.f, q = 0.f;
        #pragma unroll
        for (int w = 0; w < 4; w++) {
            s += sS[grp * 4 + w][colw];
            q += sQ[grp * 4 + w][colw];
        }
        gS[tid] = s;
        gQ[tid] = q;
    }
}

// ---------------- reduce partials + BN finalize ----------------
__global__ void reduce_bnfin64(const float* __restrict__ pS, const float* __restrict__ pQ,
                               int nblk, const float* __restrict__ g,
                               const float* __restrict__ b,
                               float* __restrict__ a, float* __restrict__ c,
                               float inv_n) {
    __shared__ float sm[256], qm[256];
    int col = blockIdx.x, tid = threadIdx.x;
    float s = 0.f, q = 0.f;
    for (int bx = tid; bx < nblk; bx += 256) {
        s += pS[bx * 64 + col];
        q += pQ[bx * 64 + col];
    }
    sm[tid] = s; qm[tid] = q;
    __syncthreads();
    for (int off = 128; off; off >>= 1) {
        if (tid < off) { sm[tid] += sm[tid + off]; qm[tid] += qm[tid + off]; }
        __syncthreads();
    }
    if (tid == 0) {
        float m = sm[0] * inv_n;
        float v = qm[0] * inv_n - m * m;
        if (v < 0.f) v = 0.f;
        float sc = g[col] * rsqrtf(v + BN_EPS);
        a[col] = sc;
        c[col] = b[col] - m * sc;
    }
}
__global__ void reduce_bnfin256(const float* __restrict__ pS, const float* __restrict__ pQ,
                                int nblk, const float* __restrict__ g,
                                const float* __restrict__ b,
                                float* __restrict__ a, float* __restrict__ c,
                                float inv_n) {
    __shared__ float sm[256], qm[256];
    int col = blockIdx.x, tid = threadIdx.x;
    int by = col >> 7, colw = col & 127;
    const float* ps = pS + (size_t)by * MAXB * 128 + colw;
    const float* pq = pQ + (size_t)by * MAXB * 128 + colw;
    float s = 0.f, q = 0.f;
    for (int bx = tid; bx < nblk; bx += 256) {
        s += ps[bx * 128];
        q += pq[bx * 128];
    }
    sm[tid] = s; qm[tid] = q;
    __syncthreads();
    for (int off = 128; off; off >>= 1) {
        if (tid < off) { sm[tid] += sm[tid + off]; qm[tid] += qm[tid + off]; }
        __syncthreads();
    }
    if (tid == 0) {
        float m = sm[0] * inv_n;
        float v = qm[0] * inv_n - m * m;
        if (v < 0.f) v = 0.f;
        float sc = g[col] * rsqrtf(v + BN_EPS);
        a[col] = sc;
        c[col] = b[col] - m * sc;
    }
}

// ---------------- act1: BN+GELU from fp16 raw h1, write fp16 ----------------
__global__ void act1_kernel(long long total) {
    long long i = ((long long)blockIdx.x * blockDim.x + threadIdx.x) * 4;
    if (i >= total) return;
    uint2 hp = *(const uint2*)((const unsigned short*)g_h1r + i);
    float2 u0 = __half22float2(*(__half2*)&hp.x);
    float2 u1 = __half22float2(*(__half2*)&hp.y);
    int c = (int)(i & (C_B - 1));
    float4 v;
    v.x = gelu_exact(fmaf(g_a1[c],     u0.x, g_c1[c]));
    v.y = gelu_exact(fmaf(g_a1[c + 1], u0.y, g_c1[c + 1]));
    v.z = gelu_exact(fmaf(g_a1[c + 2], u1.x, g_c1[c + 2]));
    v.w = gelu_exact(fmaf(g_a1[c + 3], u1.y, g_c1[c + 3]));
    *(uint2*)((unsigned short*)g_h1h + i) = round4h(v);
}

// ---------------- w3 round to fp16 (keep [k][c][d] layout) ----------------
__global__ void w3_split_kernel(const float* __restrict__ w3) {
    int i = blockIdx.x * blockDim.x + threadIdx.x;
    if (i >= K_TAP * C_B * C_B) return;
    g_w3h[i] = __float2half_rn(w3[i]);
}

// ============== GEMM1 via mma.sync fp16 (2-term W): h1 = data[N,256] @ w1[256,64] ==============
#define G1_A  0
#define G1_BH 18432
#define G1_BL 27648
#define G1_SMEM 36864

__global__ void __launch_bounds__(256) gemm1_mma_kernel(const float* __restrict__ data,
                                                        const float* __restrict__ w1, int n) {
    extern __shared__ char smem[];
    const uint32_t sb = smem_u32(smem);
    const int tid = threadIdx.x;
    const int wid = tid >> 5, lane = tid & 31;
    const int wr = wid & 3, wc = wid >> 2;
    const int row0 = blockIdx.x * 128;

    float acc[2][4][4] = {};
    const uint32_t aOff = (uint32_t)((wr * 32 + (lane & 15)) * 144 + (lane >> 4) * 16);
    const uint32_t bOff = (uint32_t)((lane & 15) * 144 + (wc * 32 + (lane >> 4) * 8) * 2);

    for (int kb = 0; kb < C_IN; kb += 64) {
        #pragma unroll
        for (int j = 0; j < 8; j++) {
            int s = tid + 256 * j;
            int r = s >> 4, f4 = s & 15;
            int rr = row0 + r; if (rr >= n) rr = n - 1;
            float4 v = *(const float4*)(data + (size_t)rr * C_IN + kb + f4 * 4);
            *(uint2*)(smem + G1_A + r * 144 + f4 * 8) = round4h(v);
        }
        #pragma unroll
        for (int j = 0; j < 4; j++) {
            int s = tid + 256 * j;
            int r = s >> 4, f4 = s & 15;
            float4 v = *(const float4*)(w1 + (size_t)(kb + r) * C_B + f4 * 4);
            uint2 hi, lo; split4h(v, &hi, &lo);
            *(uint2*)(smem + G1_BH + r * 144 + f4 * 8) = hi;
            *(uint2*)(smem + G1_BL + r * 144 + f4 * 8) = lo;
        }
        __syncthreads();

        #pragma unroll
        for (int ks = 0; ks < 4; ks++) {
            uint32_t ah[2][4], bh[2][4], bl[2][4];
            #pragma unroll
            for (int mt = 0; mt < 2; mt++)
                ldsm_x4(ah[mt], sb + G1_A + aOff + (uint32_t)(mt * 16 * 144 + ks * 32));
            #pragma unroll
            for (int nt2 = 0; nt2 < 2; nt2++) {
                uint32_t bd = sb + G1_BH + bOff + (uint32_t)(ks * 16 * 144 + nt2 * 32);
                ldsm_x4_t(bh[nt2], bd);
                ldsm_x4_t(bl[nt2], bd + (G1_BL - G1_BH));
            }
            #pragma unroll
            for (int mt = 0; mt < 2; mt++) {
                #pragma unroll
                for (int nt = 0; nt < 4; nt++) {
                    const uint32_t* ph = &bh[nt >> 1][(nt & 1) * 2];
                    const uint32_t* pl = &bl[nt >> 1][(nt & 1) * 2];
                    mma_f16(acc[mt][nt], ah[mt], ph);
                    mma_f16(acc[mt][nt], ah[mt], pl);
                }
            }
        }
        __syncthreads();
    }

    #pragma unroll
    for (int mt = 0; mt < 2; mt++) {
        int r0 = row0 + wr * 32 + mt * 16 + (lane >> 2);
        #pragma unroll
        for (int nt = 0; nt < 4; nt++) {
            int col = wc * 32 + nt * 8 + (lane & 3) * 2;
            if (r0 < n)
                *(__half2*)&g_h1r[(size_t)r0 * C_B + col] =
                    __floats2half2_rn(acc[mt][nt][0], acc[mt][nt][1]);
            if (r0 + 8 < n)
                *(__half2*)&g_h1r[(size_t)(r0 + 8) * C_B + col] =
                    __floats2half2_rn(acc[mt][nt][2], acc[mt][nt][3]);
        }
    }
    epilogue_partials<4>(acc, row0 + wr * 32, n, lane, wid, tid,
                         g_p1s + (size_t)blockIdx.x * 64,
                         g_p1q + (size_t)blockIdx.x * 64);
}

// ============== octree conv via mma.sync fp16 (1-term) + cp.async double buffering ==============
#define OB_A  0
#define OB_WH 18432
#define OB_SZ 27648
#define OFF_IDX 0
#define OFF_BUF 13824
#define OCT_SMEM (OFF_BUF + 2 * OB_SZ)   // 69120

__device__ __forceinline__ void issue_tap(uint32_t sb, int buf, int k,
                                          const int* sIdx, int tid) {
    const uint32_t base = sb + OFF_BUF + buf * OB_SZ;
    const int* idx = sIdx + (k << 7);
    #pragma unroll
    for (int j = 0; j < 4; j++) {
        int cid = tid + 256 * j;              // 0..1023
        int r = cid >> 3, q = cid & 7;
        int gr = idx[r];
        cp16(base + OB_A + (uint32_t)(r * 144 + q * 16),
             g_h1h + (size_t)gr * C_B + q * 8);
    }
    #pragma unroll
    for (int j = 0; j < 2; j++) {
        int cid = tid + 256 * j;              // 0..511
        int r = cid >> 3, q = cid & 7;
        cp16(base + OB_WH + (uint32_t)(r * 144 + q * 16),
             g_w3h + (size_t)k * 4096 + cid * 8);
    }
}

__global__ void __launch_bounds__(256) octconv_mma_kernel(const int* __restrict__ neigh,
                                                          int n) {
    extern __shared__ char smem[];
    const uint32_t sb = smem_u32(smem);
    const int tid = threadIdx.x;
    const int wid = tid >> 5, lane = tid & 31;
    const int wr = wid & 3, wc = wid >> 2;
    const int row0 = blockIdx.x * 128;

    int* sIdx = (int*)(smem + OFF_IDX);
    for (int i = tid; i < K_TAP * 128; i += 256) {
        int r = i / K_TAP, k = i - r * K_TAP;
        int nr = row0 + r;
        sIdx[k * 128 + r] = (nr < n) ? neigh[(size_t)nr * K_TAP + k] : 0;
    }
    __syncthreads();

    issue_tap(sb, 0, 0, sIdx, tid);
    cp_commit();

    float acc[2][4][4] = {};
    const uint32_t aOff = (uint32_t)((wr * 32 + (lane & 15)) * 144 + (lane >> 4) * 16);
    const uint32_t bOff = (uint32_t)((lane & 15) * 144 + (wc * 32 + (lane >> 4) * 8) * 2);

    for (int k = 0; k < K_TAP; k++) {
        const int b = k & 1;
        if (k + 1 < K_TAP) {
            issue_tap(sb, b ^ 1, k + 1, sIdx, tid);
            cp_commit();
            asm volatile("cp.async.wait_group 1;" ::: "memory");
        } else {
            asm volatile("cp.async.wait_group 0;" ::: "memory");
        }
        __syncthreads();

        const uint32_t base = sb + OFF_BUF + b * OB_SZ;
        #pragma unroll
        for (int ks = 0; ks < 4; ks++) {
            uint32_t ah[2][4], bh[2][4];
            #pragma unroll
            for (int mt = 0; mt < 2; mt++)
                ldsm_x4(ah[mt], base + OB_A + aOff + (uint32_t)(mt * 16 * 144 + ks * 32));
            #pragma unroll
            for (int nt2 = 0; nt2 < 2; nt2++)
                ldsm_x4_t(bh[nt2], base + OB_WH + bOff + (uint32_t)(ks * 16 * 144 + nt2 * 32));
            #pragma unroll
            for (int mt = 0; mt < 2; mt++) {
                #pragma unroll
                for (int nt = 0; nt < 4; nt++) {
                    const uint32_t* ph = &bh[nt >> 1][(nt & 1) * 2];
                    mma_f16(acc[mt][nt], ah[mt], ph);
                }
            }
        }
        __syncthreads();
    }

    #pragma unroll
    for (int mt = 0; mt < 2; mt++) {
        int r0 = row0 + wr * 32 + mt * 16 + (lane >> 2);
        #pragma unroll
        for (int nt = 0; nt < 4; nt++) {
            int col = wc * 32 + nt * 8 + (lane & 3) * 2;
            if (r0 < n)
                *(float2*)&g_h2[(size_t)r0 * C_B + col] =
                    make_float2(acc[mt][nt][0], acc[mt][nt][1]);
            if (r0 + 8 < n)
                *(float2*)&g_h2[(size_t)(r0 + 8) * C_B + col] =
                    make_float2(acc[mt][nt][2], acc[mt][nt][3]);
        }
    }
    epilogue_partials<4>(acc, row0 + wr * 32, n, lane, wid, tid,
                         g_p2s + (size_t)blockIdx.x * 64,
                         g_p2q + (size_t)blockIdx.x * 64);
}

// ============== GEMM2 via mma.sync fp16 (2-term W): h3 = act2(h2)[N,64] @ w2[64,256] ==============
// Single CTA per 128 rows: stage A once, sweep both 128-col W halves.
#define G2_A  0
#define G2_BH 18432
#define G2_BL (18432 + 17408)
#define G2_SMEM (18432 + 2 * 17408)   // 53248

__global__ void __launch_bounds__(256) gemm2_mma_kernel(const float* __restrict__ w2, int n) {
    extern __shared__ char smem[];
    const uint32_t sb = smem_u32(smem);
    const int tid = threadIdx.x;
    const int wid = tid >> 5, lane = tid & 31;
    const int wr = wid & 3, wc = wid >> 2;
    const int row0 = blockIdx.x * 128;

    // stage A with BN2+GELU, rounded to fp16 (once for both column halves)
    #pragma unroll
    for (int j = 0; j < 8; j++) {
        int s = tid + 256 * j;
        int r = s >> 4, f4 = s & 15;
        int rr = row0 + r; if (rr >= n) rr = n - 1;
        float4 v = *(const float4*)(g_h2 + (size_t)rr * C_B + f4 * 4);
        int c = f4 * 4;
        v.x = gelu_exact(fmaf(g_a2[c],     v.x, g_c2[c]));
        v.y = gelu_exact(fmaf(g_a2[c + 1], v.y, g_c2[c + 1]));
        v.z = gelu_exact(fmaf(g_a2[c + 2], v.z, g_c2[c + 2]));
        v.w = gelu_exact(fmaf(g_a2[c + 3], v.w, g_c2[c + 3]));
        *(uint2*)(smem + G2_A + r * 144 + f4 * 8) = round4h(v);
    }

    const uint32_t aOff = (uint32_t)((wr * 32 + (lane & 15)) * 144 + (lane >> 4) * 16);
    const uint32_t bOff = (uint32_t)((lane & 15) * 272 + (wc * 64 + (lane >> 4) * 8) * 2);

    for (int half = 0; half < 2; half++) {
        const int col0 = half * 128;
        // stage B: w2[0..63][col0..col0+127] (fp16 hi/lo, row stride 272 B)
        #pragma unroll
        for (int j = 0; j < 8; j++) {
            int s = tid + 256 * j;            // 0..2047
            int r = s >> 5, f4 = s & 31;
            float4 v = *(const float4*)(w2 + (size_t)r * C_IN + col0 + f4 * 4);
            uint2 hi, lo; split4h(v, &hi, &lo);
            *(uint2*)(smem + G2_BH + r * 272 + f4 * 8) = hi;
            *(uint2*)(smem + G2_BL + r * 272 + f4 * 8) = lo;
        }
        __syncthreads();

        float acc[2][8][4] = {};
        #pragma unroll
        for (int ks = 0; ks < 4; ks++) {
            uint32_t ah[2][4], bh[4][4], bl[4][4];
            #pragma unroll
            for (int mt = 0; mt < 2; mt++)
                ldsm_x4(ah[mt], sb + G2_A + aOff + (uint32_t)(mt * 16 * 144 + ks * 32));
            #pragma unroll
            for (int nt2 = 0; nt2 < 4; nt2++) {
                uint32_t bd = sb + G2_BH + bOff + (uint32_t)(ks * 16 * 272 + nt2 * 32);
                ldsm_x4_t(bh[nt2], bd);
                ldsm_x4_t(bl[nt2], bd + (G2_BL - G2_BH));
            }
            #pragma unroll
            for (int mt = 0; mt < 2; mt++) {
                #pragma unroll
                for (int nt = 0; nt < 8; nt++) {
                    const uint32_t* ph = &bh[nt >> 1][(nt & 1) * 2];
                    const uint32_t* pl = &bl[nt >> 1][(nt & 1) * 2];
                    mma_f16(acc[mt][nt], ah[mt], ph);
                    mma_f16(acc[mt][nt], ah[mt], pl);
                }
            }
        }

        #pragma unroll
        for (int mt = 0; mt < 2; mt++) {
            int r0 = row0 + wr * 32 + mt * 16 + (lane >> 2);
            #pragma unroll
            for (int nt = 0; nt < 8; nt++) {
                int col = col0 + wc * 64 + nt * 8 + (lane & 3) * 2;
                if (r0 < n)
                    *(__half2*)&g_h3h[(size_t)r0 * C_IN + col] =
                        __floats2half2_rn(acc[mt][nt][0], acc[mt][nt][1]);
                if (r0 + 8 < n)
                    *(__half2*)&g_h3h[(size_t)(r0 + 8) * C_IN + col] =
                        __floats2half2_rn(acc[mt][nt][2], acc[mt][nt][3]);
            }
        }
        epilogue_partials<8>(acc, row0 + wr * 32, n, lane, wid, tid,
                             g_p3s + ((size_t)half * MAXB + blockIdx.x) * 128,
                             g_p3q + ((size_t)half * MAXB + blockIdx.x) * 128);
        __syncthreads();   // all reads of B done before restaging next half
    }
}

// ---------------- epilogue: out = elu(bn3(h3_fp16) + data) ----------------
__global__ void final_kernel(const float* __restrict__ data,
                             float* __restrict__ out, long long total) {
    long long i = ((long long)blockIdx.x * blockDim.x + threadIdx.x) * 4;
    if (i >= total) return;
    uint2 hp = *(const uint2*)((const unsigned short*)g_h3h + i);
    float2 f0 = __half22float2(*(__half2*)&hp.x);
    float2 f1 = __half22float2(*(__half2*)&hp.y);
    float4 d = *(const float4*)&data[i];
    int c = (int)(i & (C_IN - 1));
    float4 h;
    float x;
    x = fmaf(g_a3[c],     f0.x, g_c3[c])     + d.x; h.x = x > 0.f ? x : expm1f(x);
    x = fmaf(g_a3[c + 1], f0.y, g_c3[c + 1]) + d.y; h.y = x > 0.f ? x : expm1f(x);
    x = fmaf(g_a3[c + 2], f1.x, g_c3[c + 2]) + d.z; h.z = x > 0.f ? x : expm1f(x);
    x = fmaf(g_a3[c + 3], f1.y, g_c3[c + 3]) + d.w; h.w = x > 0.f ? x : expm1f(x);
    *(float4*)&out[i] = h;
}

// ---------------- launch ----------------
extern "C" void kernel_launch(void* const* d_in, const int* in_sizes, int n_in,
                              void* d_out, int out_size) {
    const float* data  = (const float*)d_in[0];
    const int*   neigh = (const int*)d_in[1];
    const float* w1 = (const float*)d_in[2];
    const float* g1 = (const float*)d_in[3];
    const float* b1 = (const float*)d_in[4];
    const float* w3 = (const float*)d_in[5];
    const float* g3 = (const float*)d_in[6];
    const float* b3 = (const float*)d_in[7];
    const float* w2 = (const float*)d_in[8];
    const float* g2 = (const float*)d_in[9];
    const float* b2 = (const float*)d_in[10];
    float* out = (float*)d_out;

    const int n = in_sizes[0] / C_IN;
    const float inv_n = 1.0f / (float)n;
    const int nblk128 = (n + 127) / 128;
    const long long tot_b = (long long)n * C_B;
    const long long tot_c = (long long)n * C_IN;

    float *a1p, *c1p, *a2p, *c2p, *a3p, *c3p;
    cudaGetSymbolAddress((void**)&a1p, g_a1); cudaGetSymbolAddress((void**)&c1p, g_c1);
    cudaGetSymbolAddress((void**)&a2p, g_a2); cudaGetSymbolAddress((void**)&c2p, g_c2);
    cudaGetSymbolAddress((void**)&a3p, g_a3); cudaGetSymbolAddress((void**)&c3p, g_c3);
    float *p1s, *p1q, *p2s, *p2q, *p3s, *p3q;
    cudaGetSymbolAddress((void**)&p1s, g_p1s); cudaGetSymbolAddress((void**)&p1q, g_p1q);
    cudaGetSymbolAddress((void**)&p2s, g_p2s); cudaGetSymbolAddress((void**)&p2q, g_p2q);
    cudaGetSymbolAddress((void**)&p3s, g_p3s); cudaGetSymbolAddress((void**)&p3q, g_p3q);

    cudaFuncSetAttribute(gemm1_mma_kernel,
                         cudaFuncAttributeMaxDynamicSharedMemorySize, G1_SMEM);
    cudaFuncSetAttribute(octconv_mma_kernel,
                         cudaFuncAttributeMaxDynamicSharedMemorySize, OCT_SMEM);
    cudaFuncSetAttribute(gemm2_mma_kernel,
                         cudaFuncAttributeMaxDynamicSharedMemorySize, G2_SMEM);

    w3_split_kernel<<<(K_TAP * C_B * C_B + 255) / 256, 256>>>(w3);

    gemm1_mma_kernel<<<nblk128, 256, G1_SMEM>>>(data, w1, n);
    reduce_bnfin64<<<64, 256>>>(p1s, p1q, nblk128, g1, b1, a1p, c1p, inv_n);
    act1_kernel<<<(int)((tot_b / 4 + 255) / 256), 256>>>(tot_b);

    octconv_mma_kernel<<<nblk128, 256, OCT_SMEM>>>(neigh, n);
    reduce_bnfin64<<<64, 256>>>(p2s, p2q, nblk128, g3, b3, a2p, c2p, inv_n);

    gemm2_mma_kernel<<<nblk128, 256, G2_SMEM>>>(w2, n);
    reduce_bnfin256<<<256, 256>>>(p3s, p3q, nblk128, g2, b2, a3p, c3p, inv_n);

    final_kernel<<<(int)((tot_c / 4 + 255) / 256), 256>>>(data, out, tot_c);
}